// round 15
// baseline (speedup 1.0000x reference)
#include <cuda_runtime.h>
#include <cuda_fp16.h>
#include <math.h>
#include <stdint.h>

// ---------------------------------------------------------------------------
// Problem: u (8,4096,1024) f32. Outputs: y (8,4096,1024), gamma, final.
// gamma kernel emits u in fp16; fused GEMM computes
//   C1[m] = u[m]   @ WB ^T (cols bj..bj+63)   (warps 0-3)
//   C2[m] = u[m+1] @ WBf^T (cols bj..bj+63)   (warps 4-7, +1 row shift)
// from ONE shared 129-row A tile, then writes y = g*(xf+xb)+(1-g)*u directly.
// 256 thr/CTA, 3-stage cp.async (loads interleaved into ks steps),
// one barrier per chunk, 2 CTAs/SM.
// ---------------------------------------------------------------------------
#define BB 8
#define TT 4096
#define DD 1024
#define ROWS (BB * TT)              // 32768  (M)
#define KK   DD                     // 1024   (K)
#define Y_ELEMS   (ROWS * DD)
#define G_ELEMS   (ROWS)

// GEMM tiling
#define BM 128
#define XN 64                        // V-columns per CTA (each of C1, C2)
#define BK 64
#define STAGES 3
#define NCHUNK (KK / BK)             // 16
#define OFF_A 0                      // 129 rows x 128B
#define OFF_B 16640
#define STAGE_BYTES 33024            // A(16640) + B(16384)
#define SMEM_DYN (STAGES * STAGE_BYTES)   // 99072
#define CS_STRIDE 68                 // fp32 staging stride (bank-friendly)

// Device-global scratch (no cudaMalloc anywhere)
__device__ __half g_Af[(size_t)ROWS * KK];       // 64 MiB  (u in fp16)
__device__ __half g_Bf[(size_t)2 * DD * KK];     // 4 MiB: rows 0..1023 WB, 1024.. WBf
__device__ float  g_vecs[4 * DD];                // a1 | a2 | cB | cBf
__device__ float  g_part[16][4][DD];             // precompute partials
__device__ float  g_gamma[ROWS];

// ---------------------------------------------------------------------------
// PTX helpers (sm_80-class only: cp.async, ldmatrix, mma.sync)
// ---------------------------------------------------------------------------
__device__ __forceinline__ uint32_t smem_u32(const void* p) {
    uint32_t a;
    asm("{ .reg .u64 t; cvta.to.shared.u64 t, %1; cvt.u32.u64 %0, t; }"
        : "=r"(a) : "l"(p));
    return a;
}
__device__ __forceinline__ void cpasync16(uint32_t dst, const void* src) {
    asm volatile("cp.async.cg.shared.global [%0], [%1], 16;" :: "r"(dst), "l"(src));
}
#define CP_COMMIT() asm volatile("cp.async.commit_group;" ::: "memory")
#define CP_WAIT_1() asm volatile("cp.async.wait_group 1;" ::: "memory")
#define CP_WAIT_0() asm volatile("cp.async.wait_group 0;" ::: "memory")

__device__ __forceinline__ void ldm_x4(uint32_t* r, uint32_t addr) {
    asm volatile("ldmatrix.sync.aligned.m8n8.x4.shared.b16 {%0,%1,%2,%3}, [%4];"
                 : "=r"(r[0]), "=r"(r[1]), "=r"(r[2]), "=r"(r[3]) : "r"(addr));
}
__device__ __forceinline__ void mma16816(float* c, const uint32_t* a,
                                         const uint32_t* b) {
    asm volatile("mma.sync.aligned.m16n8k16.row.col.f32.f16.f16.f32 "
                 "{%0,%1,%2,%3}, {%4,%5,%6,%7}, {%8,%9}, {%0,%1,%2,%3};"
                 : "+f"(c[0]), "+f"(c[1]), "+f"(c[2]), "+f"(c[3])
                 : "r"(a[0]), "r"(a[1]), "r"(a[2]), "r"(a[3]),
                   "r"(b[0]), "r"(b[1]));
}

// ---------------------------------------------------------------------------
// K0: [WB;WBf] -> fp16.
// ---------------------------------------------------------------------------
__global__ void convert_w_kernel(const float* __restrict__ WB,
                                 const float* __restrict__ WBf) {
    size_t i = ((size_t)blockIdx.x * 256 + threadIdx.x) * 4;
    const float* src = (i < (size_t)DD * DD) ? (WB + i) : (WBf + i - (size_t)DD * DD);
    float4 x = *(const float4*)src;
    union { __half h[4]; uint2 v; } H;
    H.h[0] = __float2half_rn(x.x);  H.h[1] = __float2half_rn(x.y);
    H.h[2] = __float2half_rn(x.z);  H.h[3] = __float2half_rn(x.w);
    *(uint2*)(g_Bf + i) = H.v;
}

// ---------------------------------------------------------------------------
// K1a/K1b: precompute a1 = w1@WB, a2 = w2@WBf, cB = Wc@WB, cBf = Wc@WBf.
// Two-phase, 64 CTAs, no atomics (deterministic): partials then reduce.
// ---------------------------------------------------------------------------
__global__ void precompute_partial_kernel(const float* __restrict__ WB,
                                          const float* __restrict__ WBf,
                                          const float* __restrict__ w1,
                                          const float* __restrict__ w2,
                                          const float* __restrict__ Wc) {
    int d  = blockIdx.x * 256 + threadIdx.x;   // 0..1023
    int e0 = blockIdx.y * 64;
    float a1 = 0.f, a2 = 0.f, cB = 0.f, cBf = 0.f;
#pragma unroll 8
    for (int e = e0; e < e0 + 64; ++e) {
        float wb = WB[e * DD + d];
        float wf = WBf[e * DD + d];
        a1  += w1[e] * wb;
        cB  += Wc[e] * wb;
        a2  += w2[e] * wf;
        cBf += Wc[e] * wf;
    }
    g_part[blockIdx.y][0][d] = a1;
    g_part[blockIdx.y][1][d] = a2;
    g_part[blockIdx.y][2][d] = cB;
    g_part[blockIdx.y][3][d] = cBf;
}

__global__ void precompute_reduce_kernel() {
    int d = blockIdx.x * 256 + threadIdx.x;    // 0..1023
#pragma unroll
    for (int v = 0; v < 4; ++v) {
        float s = 0.f;
#pragma unroll
        for (int k = 0; k < 16; ++k) s += g_part[k][v][d];
        g_vecs[v * DD + d] = s;
    }
}

// ---------------------------------------------------------------------------
// K2: gamma + final (fp32 exact dots) + emit u row in fp16 (feeds the GEMM).
// One warp per row. (R13-proven version.)
// ---------------------------------------------------------------------------
__global__ __launch_bounds__(256, 5)
void gamma_final_kernel(const float* __restrict__ u,
                        const float* __restrict__ w1,
                        const float* __restrict__ w2,
                        const float* __restrict__ bias,
                        const float* __restrict__ Wc,
                        float* __restrict__ gamma_out,
                        float* __restrict__ final_out) {
    int row  = blockIdx.x * 8 + (threadIdx.x >> 5);
    int lane = threadIdx.x & 31;
    int t = row & (TT - 1);

    const float* u1 = u + (size_t)row * DD;
    const float* u2 = (t == TT - 1) ? u1 : u1 + DD;
    const float* vS1 = (t == 0)      ? w1 : (g_vecs + 0);
    const float* vCf = (t == 0)      ? Wc : (g_vecs + 2 * DD);
    const float* vS2 = (t == TT - 1) ? w2 : (g_vecs + DD);
    const float* vCb = (t == TT - 1) ? Wc : (g_vecs + 3 * DD);

    float s1 = 0.f, s2 = 0.f, cf = 0.f, cb = 0.f, cu = 0.f;
#pragma unroll
    for (int it = 0; it < 8; ++it) {
        int i = lane * 4 + it * 128;
        float4 uu = *(const float4*)(u1 + i);
        float4 vv = *(const float4*)(u2 + i);
        float4 x1 = *(const float4*)(vS1 + i);
        float4 xc = *(const float4*)(vCf + i);
        float4 wc = *(const float4*)(Wc + i);
        float4 x2 = *(const float4*)(vS2 + i);
        float4 xb = *(const float4*)(vCb + i);
        union { __half h[4]; uint2 v; } H;
        H.h[0] = __float2half_rn(uu.x);  H.h[1] = __float2half_rn(uu.y);
        H.h[2] = __float2half_rn(uu.z);  H.h[3] = __float2half_rn(uu.w);
        *(uint2*)(g_Af + (size_t)row * DD + i) = H.v;

        s1 += uu.x * x1.x + uu.y * x1.y + uu.z * x1.z + uu.w * x1.w;
        cf += uu.x * xc.x + uu.y * xc.y + uu.z * xc.z + uu.w * xc.w;
        cu += uu.x * wc.x + uu.y * wc.y + uu.z * wc.z + uu.w * wc.w;
        s2 += vv.x * x2.x + vv.y * x2.y + vv.z * x2.z + vv.w * x2.w;
        cb += vv.x * xb.x + vv.y * xb.y + vv.z * xb.z + vv.w * xb.w;
    }
#pragma unroll
    for (int off = 16; off > 0; off >>= 1) {
        s1 += __shfl_down_sync(0xffffffffu, s1, off);
        s2 += __shfl_down_sync(0xffffffffu, s2, off);
        cf += __shfl_down_sync(0xffffffffu, cf, off);
        cb += __shfl_down_sync(0xffffffffu, cb, off);
        cu += __shfl_down_sync(0xffffffffu, cu, off);
    }
    if (lane == 0) {
        float g   = 1.f / (1.f + expf(-(s1 + s2 + bias[0])));
        float fin = 1.f / (1.f + expf(-(g * (cf + cb) + (1.f - g) * cu)));
        g_gamma[row]   = g;
        gamma_out[row] = g;
        final_out[row] = fin;
    }
}

// ---------------------------------------------------------------------------
// K3: fused HMMA GEMM + y epilogue. 256 threads, 2 CTAs/SM, one barrier/chunk.
// cp.async for chunk c+2 is interleaved into the 4 ks steps of chunk c
// (one quarter per ks, issued between LDSM and HMMA) to avoid the
// post-barrier LDGSTS burst colliding with ldmatrix on the LSU/L1 port.
// grid (1024/64 = 16, 32768/128 = 256).
// ---------------------------------------------------------------------------
__global__ __launch_bounds__(256, 2)
void gemm_fused_kernel(const float* __restrict__ u, float* __restrict__ y) {
    extern __shared__ __align__(128) char dsm[];
    const uint32_t sbase = smem_u32(dsm);

    const int tid  = threadIdx.x;
    const int wid  = tid >> 5;
    const int lane = tid & 31;
    const int bm = blockIdx.y * BM;
    const int bj = blockIdx.x * XN;     // V column offset (0..960)

    const int grp = wid >> 2;           // 0: C1 (row m), 1: C2 (row m+1)
    const int w2  = wid & 3;
    const int wm  = (w2 >> 1) * 64;     // warp m offset (0/64)
    const int wn  = (w2 & 1) * 32;      // warp n offset within 64 (0/32)

    const int lrow = tid >> 3;          // 0..31 (+j*32)
    const int lchk = tid & 7;

    // one quarter (j) of a stage's loads: 2 cp.async per thread
    auto load_quarter = [&](int kchunk, int slot, int j) {
        uint32_t sb = sbase + slot * STAGE_BYTES;
        int kb = kchunk * BK;
        int r = lrow + j * 32;
        uint32_t so = (uint32_t)(r * 128) + (uint32_t)((lchk ^ (r & 7)) << 4);
        int rb = bj + r + ((r >> 6) * (DD - XN));   // rows 0-63: WB, 64-127: WBf
        cpasync16(sb + OFF_A + so, g_Af + (size_t)(bm + r) * KK + kb + lchk * 8);
        cpasync16(sb + OFF_B + so, g_Bf + (size_t)rb * KK + kb + lchk * 8);
    };
    auto load_extra = [&](int kchunk, int slot) {    // A row 128 (clamped)
        if (tid < 8) {
            uint32_t sb = sbase + slot * STAGE_BYTES;
            int kb = kchunk * BK;
            int ra = bm + 128;  if (ra > ROWS - 1) ra = ROWS - 1;
            cpasync16(sb + OFF_A + 128 * 128 + tid * 16,
                      g_Af + (size_t)ra * KK + kb + tid * 8);
        }
    };
    auto load_stage = [&](int kchunk, int slot) {
#pragma unroll
        for (int j = 0; j < 4; ++j) load_quarter(kchunk, slot, j);
        load_extra(kchunk, slot);
    };

    // -- per-thread ldmatrix bases (A row gets +grp shift) --
    uint32_t a_base[4], b_base[2];
    int a_rx[4], b_rx[2];
    const int a_ch = lane >> 4;
    const int b_ch = (lane >> 3) & 1;
#pragma unroll
    for (int mi = 0; mi < 4; ++mi) {
        int r = wm + mi * 16 + (lane & 15) + grp;
        a_base[mi] = OFF_A + (uint32_t)(r * 128);
        a_rx[mi] = r & 7;
    }
#pragma unroll
    for (int p = 0; p < 2; ++p) {
        int r = grp * 64 + wn + p * 16 + (lane & 7) + ((lane >> 4) << 3);
        b_base[p] = OFF_B + (uint32_t)(r * 128);
        b_rx[p] = r & 7;
    }

    float acc[4][4][4];
#pragma unroll
    for (int mi = 0; mi < 4; ++mi)
#pragma unroll
        for (int nj = 0; nj < 4; ++nj)
#pragma unroll
            for (int q = 0; q < 4; ++q) acc[mi][nj][q] = 0.f;

    load_stage(0, 0); CP_COMMIT();
    load_stage(1, 1); CP_COMMIT();

    for (int c = 0; c < NCHUNK; ++c) {
        if (c < NCHUNK - 1) CP_WAIT_1(); else CP_WAIT_0();
        __syncthreads();

        const uint32_t slot = sbase + (uint32_t)((c % STAGES) * STAGE_BYTES);
        const bool prefetch = (c + 2 < NCHUNK);
        const int  pslot    = (c + 2) % STAGES;

#pragma unroll
        for (int ks = 0; ks < 4; ++ks) {
            const int kc = ks * 2;
            uint32_t af[16], bf[8];
#pragma unroll
            for (int mi = 0; mi < 4; ++mi)
                ldm_x4(af + mi * 4, slot + a_base[mi] + (uint32_t)(((kc + a_ch) ^ a_rx[mi]) << 4));
#pragma unroll
            for (int p = 0; p < 2; ++p)
                ldm_x4(bf + p * 4, slot + b_base[p] + (uint32_t)(((kc + b_ch) ^ b_rx[p]) << 4));

            if (prefetch) {                 // fill LSU while HMMA runs
                load_quarter(c + 2, pslot, ks);
                if (ks == 0) load_extra(c + 2, pslot);
            }
#pragma unroll
            for (int mi = 0; mi < 4; ++mi)
#pragma unroll
                for (int nj = 0; nj < 4; ++nj)
                    mma16816(acc[mi][nj], af + mi * 4, bf + nj * 2);
        }
        if (prefetch) CP_COMMIT();
    }
    __syncthreads();   // everyone done reading SMEM before Cs staging reuses it

    // -- epilogue: stage C1/C2 (fp32) + gamma to smem, then write y --
    float* Cs = (float*)dsm;                       // [2][128][CS_STRIDE]
    float* Gs = Cs + 2 * 128 * CS_STRIDE;          // [128]
    const int lr = lane >> 2;
    const int lc = (lane & 3) * 2;
    float* Cg = Cs + (size_t)grp * 128 * CS_STRIDE;
#pragma unroll
    for (int mi = 0; mi < 4; ++mi) {
#pragma unroll
        for (int nj = 0; nj < 4; ++nj) {
            float* p0 = Cg + (size_t)(wm + mi * 16 + lr) * CS_STRIDE + wn + nj * 8 + lc;
            *(float2*)p0                    = make_float2(acc[mi][nj][0], acc[mi][nj][1]);
            *(float2*)(p0 + 8 * CS_STRIDE)  = make_float2(acc[mi][nj][2], acc[mi][nj][3]);
        }
    }
    if (tid < 128) Gs[tid] = g_gamma[bm + tid];
    __syncthreads();

#pragma unroll
    for (int it = 0; it < 8; ++it) {
        int idx = tid + it * 256;          // 0..2047  (128 rows x 16 col-quads)
        int row = idx >> 4;
        int c4  = (idx & 15) * 4;
        int m = bm + row;
        int t = m & (TT - 1);
        float g  = Gs[row];
        float og = 1.f - g;

        float4 uu = *(const float4*)(u + (size_t)m * DD + bj + c4);
        float4 c1 = *(const float4*)(Cs + (size_t)row * CS_STRIDE + c4);
        float4 c2 = *(const float4*)(Cs + (size_t)(128 + row) * CS_STRIDE + c4);
        float4 xf = (t == 0)      ? uu : c1;
        float4 xb = (t == TT - 1) ? uu : c2;

        float4 out;
        out.x = g * (xf.x + xb.x) + og * uu.x;
        out.y = g * (xf.y + xb.y) + og * uu.y;
        out.z = g * (xf.z + xb.z) + og * uu.z;
        out.w = g * (xf.w + xb.w) + og * uu.w;
        *(float4*)(y + (size_t)m * DD + bj + c4) = out;
    }
}

// ---------------------------------------------------------------------------
// kernel_launch: inputs 0:u 1:WA(dead) 2:WB 3:WAf(dead) 4:WBf 5:w1 6:w2 7:b 8:Wc
// Output: [y | gamma | final] flattened f32.
// ---------------------------------------------------------------------------
extern "C" void kernel_launch(void* const* d_in, const int* in_sizes, int n_in,
                              void* d_out, int out_size) {
    (void)in_sizes; (void)n_in; (void)out_size;
    const float* u   = (const float*)d_in[0];
    const float* WB  = (const float*)d_in[2];
    const float* WBf = (const float*)d_in[4];
    const float* w1  = (const float*)d_in[5];
    const float* w2  = (const float*)d_in[6];
    const float* b   = (const float*)d_in[7];
    const float* Wc  = (const float*)d_in[8];

    float* y         = (float*)d_out;
    float* gamma_out = y + Y_ELEMS;
    float* final_out = gamma_out + G_ELEMS;

    cudaFuncSetAttribute(gemm_fused_kernel,
                         cudaFuncAttributeMaxDynamicSharedMemorySize, SMEM_DYN);

    convert_w_kernel<<<(2 * DD * KK) / 1024, 256>>>(WB, WBf);
    precompute_partial_kernel<<<dim3(DD / 256, 16), 256>>>(WB, WBf, w1, w2, Wc);
    precompute_reduce_kernel<<<DD / 256, 256>>>();
    gamma_final_kernel<<<ROWS / 8, 256>>>(u, w1, w2, b, Wc, gamma_out, final_out);
    gemm_fused_kernel<<<dim3(DD / XN, ROWS / BM), 256, SMEM_DYN>>>(u, y);
}

// round 16
// speedup vs baseline: 1.0356x; 1.0356x over previous
#include <cuda_runtime.h>
#include <cuda_fp16.h>
#include <math.h>
#include <stdint.h>

// ---------------------------------------------------------------------------
// Problem: u (8,4096,1024) f32. Outputs: y (8,4096,1024), gamma, final.
// gamma kernel (SMEM-resident vectors) emits u in fp16; fused GEMM computes
//   C1[m] = u[m]   @ WB ^T (cols bj..bj+63)   (warps 0-3)
//   C2[m] = u[m+1] @ WBf^T (cols bj..bj+63)   (warps 4-7, +1 row shift)
// from ONE shared 129-row A tile, then writes y = g*(xf+xb)+(1-g)*u directly.
// GEMM identical to R13 (330us proven). 256 thr/CTA, 3-stage, 2 CTAs/SM.
// ---------------------------------------------------------------------------
#define BB 8
#define TT 4096
#define DD 1024
#define ROWS (BB * TT)              // 32768  (M)
#define KK   DD                     // 1024   (K)
#define Y_ELEMS   (ROWS * DD)
#define G_ELEMS   (ROWS)

// GEMM tiling
#define BM 128
#define XN 64                        // V-columns per CTA (each of C1, C2)
#define BK 64
#define STAGES 3
#define NCHUNK (KK / BK)             // 16
#define OFF_A 0                      // 129 rows x 128B
#define OFF_B 16640
#define STAGE_BYTES 33024            // A(16640) + B(16384)
#define SMEM_DYN (STAGES * STAGE_BYTES)   // 99072
#define CS_STRIDE 68                 // fp32 staging stride (bank-friendly)

// Device-global scratch (no cudaMalloc anywhere)
__device__ __half g_Af[(size_t)ROWS * KK];       // 64 MiB  (u in fp16)
__device__ __half g_Bf[(size_t)2 * DD * KK];     // 4 MiB: rows 0..1023 WB, 1024.. WBf
__device__ float  g_vecs[4 * DD];                // a1 | a2 | cB | cBf
__device__ float  g_part[16][4][DD];             // precompute partials
__device__ float  g_gamma[ROWS];

// ---------------------------------------------------------------------------
// PTX helpers (sm_80-class only: cp.async, ldmatrix, mma.sync)
// ---------------------------------------------------------------------------
__device__ __forceinline__ uint32_t smem_u32(const void* p) {
    uint32_t a;
    asm("{ .reg .u64 t; cvta.to.shared.u64 t, %1; cvt.u32.u64 %0, t; }"
        : "=r"(a) : "l"(p));
    return a;
}
__device__ __forceinline__ void cpasync16(uint32_t dst, const void* src) {
    asm volatile("cp.async.cg.shared.global [%0], [%1], 16;" :: "r"(dst), "l"(src));
}
#define CP_COMMIT() asm volatile("cp.async.commit_group;" ::: "memory")
#define CP_WAIT_1() asm volatile("cp.async.wait_group 1;" ::: "memory")
#define CP_WAIT_0() asm volatile("cp.async.wait_group 0;" ::: "memory")

__device__ __forceinline__ void ldm_x4(uint32_t* r, uint32_t addr) {
    asm volatile("ldmatrix.sync.aligned.m8n8.x4.shared.b16 {%0,%1,%2,%3}, [%4];"
                 : "=r"(r[0]), "=r"(r[1]), "=r"(r[2]), "=r"(r[3]) : "r"(addr));
}
__device__ __forceinline__ void mma16816(float* c, const uint32_t* a,
                                         const uint32_t* b) {
    asm volatile("mma.sync.aligned.m16n8k16.row.col.f32.f16.f16.f32 "
                 "{%0,%1,%2,%3}, {%4,%5,%6,%7}, {%8,%9}, {%0,%1,%2,%3};"
                 : "+f"(c[0]), "+f"(c[1]), "+f"(c[2]), "+f"(c[3])
                 : "r"(a[0]), "r"(a[1]), "r"(a[2]), "r"(a[3]),
                   "r"(b[0]), "r"(b[1]));
}
__device__ __forceinline__ float dot4(float4 a, float4 b) {
    return fmaf(a.x, b.x, fmaf(a.y, b.y, fmaf(a.z, b.z, a.w * b.w)));
}

// ---------------------------------------------------------------------------
// K0: [WB;WBf] -> fp16.
// ---------------------------------------------------------------------------
__global__ void convert_w_kernel(const float* __restrict__ WB,
                                 const float* __restrict__ WBf) {
    size_t i = ((size_t)blockIdx.x * 256 + threadIdx.x) * 4;
    const float* src = (i < (size_t)DD * DD) ? (WB + i) : (WBf + i - (size_t)DD * DD);
    float4 x = *(const float4*)src;
    union { __half h[4]; uint2 v; } H;
    H.h[0] = __float2half_rn(x.x);  H.h[1] = __float2half_rn(x.y);
    H.h[2] = __float2half_rn(x.z);  H.h[3] = __float2half_rn(x.w);
    *(uint2*)(g_Bf + i) = H.v;
}

// ---------------------------------------------------------------------------
// K1a/K1b: precompute a1 = w1@WB, a2 = w2@WBf, cB = Wc@WB, cBf = Wc@WBf.
// Two-phase, 64 CTAs, no atomics (deterministic): partials then reduce.
// ---------------------------------------------------------------------------
__global__ void precompute_partial_kernel(const float* __restrict__ WB,
                                          const float* __restrict__ WBf,
                                          const float* __restrict__ w1,
                                          const float* __restrict__ w2,
                                          const float* __restrict__ Wc) {
    int d  = blockIdx.x * 256 + threadIdx.x;   // 0..1023
    int e0 = blockIdx.y * 64;
    float a1 = 0.f, a2 = 0.f, cB = 0.f, cBf = 0.f;
#pragma unroll 8
    for (int e = e0; e < e0 + 64; ++e) {
        float wb = WB[e * DD + d];
        float wf = WBf[e * DD + d];
        a1  += w1[e] * wb;
        cB  += Wc[e] * wb;
        a2  += w2[e] * wf;
        cBf += Wc[e] * wf;
    }
    g_part[blockIdx.y][0][d] = a1;
    g_part[blockIdx.y][1][d] = a2;
    g_part[blockIdx.y][2][d] = cB;
    g_part[blockIdx.y][3][d] = cBf;
}

__global__ void precompute_reduce_kernel() {
    int d = blockIdx.x * 256 + threadIdx.x;    // 0..1023
#pragma unroll
    for (int v = 0; v < 4; ++v) {
        float s = 0.f;
#pragma unroll
        for (int k = 0; k < 16; ++k) s += g_part[k][v][d];
        g_vecs[v * DD + d] = s;
    }
}

// ---------------------------------------------------------------------------
// K2: gamma + final + fp16 u emit. One warp per row; the 5 broadcast vectors
// (a1,a2,cB,cBf,Wc) plus w1,w2 staged in SMEM (28 KB) -> LDS instead of L1.
// Boundary rows: s1/s2 from extra u.w1 / u.w2 dots; cf/cb collapse to cu
// (bit-identical to old vCf=Wc / vCb=Wc paths since u2==u1 at t==T-1).
// ---------------------------------------------------------------------------
__global__ __launch_bounds__(256, 5)
void gamma_final_kernel(const float* __restrict__ u,
                        const float* __restrict__ w1,
                        const float* __restrict__ w2,
                        const float* __restrict__ bias,
                        const float* __restrict__ Wc,
                        float* __restrict__ gamma_out,
                        float* __restrict__ final_out) {
    __shared__ __align__(16) float sv[7 * DD];   // a1|a2|cB|cBf|Wc|w1|w2

    {   // cooperative stage: one float4 per thread per vector
        int i = threadIdx.x * 4;
        *(float4*)(sv + 0 * DD + i) = *(const float4*)(g_vecs + i);
        *(float4*)(sv + 1 * DD + i) = *(const float4*)(g_vecs + DD + i);
        *(float4*)(sv + 2 * DD + i) = *(const float4*)(g_vecs + 2 * DD + i);
        *(float4*)(sv + 3 * DD + i) = *(const float4*)(g_vecs + 3 * DD + i);
        *(float4*)(sv + 4 * DD + i) = *(const float4*)(Wc + i);
        *(float4*)(sv + 5 * DD + i) = *(const float4*)(w1 + i);
        *(float4*)(sv + 6 * DD + i) = *(const float4*)(w2 + i);
    }
    __syncthreads();

    int row  = blockIdx.x * 8 + (threadIdx.x >> 5);
    int lane = threadIdx.x & 31;
    int t = row & (TT - 1);
    const bool is_t0 = (t == 0);
    const bool is_tL = (t == TT - 1);

    const float* u1 = u + (size_t)row * DD;
    const float* u2 = is_tL ? u1 : u1 + DD;

    float s1 = 0.f, s2 = 0.f, cf = 0.f, cb = 0.f, cu = 0.f, sb = 0.f;
#pragma unroll
    for (int it = 0; it < 8; ++it) {
        int i = lane * 4 + it * 128;
        float4 uu = *(const float4*)(u1 + i);
        float4 vv = *(const float4*)(u2 + i);
        float4 x1 = *(const float4*)(sv + 0 * DD + i);
        float4 x2 = *(const float4*)(sv + 1 * DD + i);
        float4 xc = *(const float4*)(sv + 2 * DD + i);
        float4 xb = *(const float4*)(sv + 3 * DD + i);
        float4 wc = *(const float4*)(sv + 4 * DD + i);

        union { __half h[4]; uint2 v; } H;
        H.h[0] = __float2half_rn(uu.x);  H.h[1] = __float2half_rn(uu.y);
        H.h[2] = __float2half_rn(uu.z);  H.h[3] = __float2half_rn(uu.w);
        *(uint2*)(g_Af + (size_t)row * DD + i) = H.v;

        s1 += dot4(uu, x1);
        s2 += dot4(vv, x2);
        cf += dot4(uu, xc);
        cb += dot4(vv, xb);
        cu += dot4(uu, wc);
        if (is_t0) sb += dot4(uu, *(const float4*)(sv + 5 * DD + i));  // u.w1
        if (is_tL) sb += dot4(uu, *(const float4*)(sv + 6 * DD + i));  // u.w2
    }
#pragma unroll
    for (int off = 16; off > 0; off >>= 1) {
        s1 += __shfl_down_sync(0xffffffffu, s1, off);
        s2 += __shfl_down_sync(0xffffffffu, s2, off);
        cf += __shfl_down_sync(0xffffffffu, cf, off);
        cb += __shfl_down_sync(0xffffffffu, cb, off);
        cu += __shfl_down_sync(0xffffffffu, cu, off);
        sb += __shfl_down_sync(0xffffffffu, sb, off);
    }
    if (lane == 0) {
        if (is_t0) { s1 = sb; cf = cu; }
        if (is_tL) { s2 = sb; cb = cu; }
        float g   = 1.f / (1.f + expf(-(s1 + s2 + bias[0])));
        float fin = 1.f / (1.f + expf(-(g * (cf + cb) + (1.f - g) * cu)));
        g_gamma[row]   = g;
        gamma_out[row] = g;
        final_out[row] = fin;
    }
}

// ---------------------------------------------------------------------------
// K3: fused HMMA GEMM + y epilogue. 256 threads, 2 CTAs/SM, ONE barrier/chunk.
// (exact R13 version, 330us proven)  grid (16, 256).
// ---------------------------------------------------------------------------
__global__ __launch_bounds__(256, 2)
void gemm_fused_kernel(const float* __restrict__ u, float* __restrict__ y) {
    extern __shared__ __align__(128) char dsm[];
    const uint32_t sbase = smem_u32(dsm);

    const int tid  = threadIdx.x;
    const int wid  = tid >> 5;
    const int lane = tid & 31;
    const int bm = blockIdx.y * BM;
    const int bj = blockIdx.x * XN;     // V column offset (0..960)

    const int grp = wid >> 2;           // 0: C1 (row m), 1: C2 (row m+1)
    const int w2  = wid & 3;
    const int wm  = (w2 >> 1) * 64;     // warp m offset (0/64)
    const int wn  = (w2 & 1) * 32;      // warp n offset within 64 (0/32)

    const int lrow = tid >> 3;          // 0..31 (+j*32)
    const int lchk = tid & 7;
    auto load_stage = [&](int kchunk, int slot) {
        uint32_t sb = sbase + slot * STAGE_BYTES;
        int kb = kchunk * BK;
#pragma unroll
        for (int j = 0; j < 4; ++j) {
            int r = lrow + j * 32;
            uint32_t so = (uint32_t)(r * 128) + (uint32_t)((lchk ^ (r & 7)) << 4);
            int rb = bj + r + ((r >> 6) * (DD - XN));   // rows 0-63: WB, 64-127: WBf
            cpasync16(sb + OFF_A + so, g_Af + (size_t)(bm + r) * KK + kb + lchk * 8);
            cpasync16(sb + OFF_B + so, g_Bf + (size_t)rb * KK + kb + lchk * 8);
        }
        if (tid < 8) {                  // A row 128 (clamped at last CTA)
            int ra = bm + 128;  if (ra > ROWS - 1) ra = ROWS - 1;
            cpasync16(sb + OFF_A + 128 * 128 + tid * 16,
                      g_Af + (size_t)ra * KK + kb + tid * 8);
        }
    };

    uint32_t a_base[4], b_base[2];
    int a_rx[4], b_rx[2];
    const int a_ch = lane >> 4;
    const int b_ch = (lane >> 3) & 1;
#pragma unroll
    for (int mi = 0; mi < 4; ++mi) {
        int r = wm + mi * 16 + (lane & 15) + grp;
        a_base[mi] = OFF_A + (uint32_t)(r * 128);
        a_rx[mi] = r & 7;
    }
#pragma unroll
    for (int p = 0; p < 2; ++p) {
        int r = grp * 64 + wn + p * 16 + (lane & 7) + ((lane >> 4) << 3);
        b_base[p] = OFF_B + (uint32_t)(r * 128);
        b_rx[p] = r & 7;
    }

    float acc[4][4][4];
#pragma unroll
    for (int mi = 0; mi < 4; ++mi)
#pragma unroll
        for (int nj = 0; nj < 4; ++nj)
#pragma unroll
            for (int q = 0; q < 4; ++q) acc[mi][nj][q] = 0.f;

    load_stage(0, 0); CP_COMMIT();
    load_stage(1, 1); CP_COMMIT();

    for (int c = 0; c < NCHUNK; ++c) {
        if (c < NCHUNK - 1) CP_WAIT_1(); else CP_WAIT_0();
        __syncthreads();

        if (c + 2 < NCHUNK) {
            load_stage(c + 2, (c + 2) % STAGES);
            CP_COMMIT();
        }

        const uint32_t slot = sbase + (uint32_t)((c % STAGES) * STAGE_BYTES);

#pragma unroll
        for (int ks = 0; ks < 4; ++ks) {
            const int kc = ks * 2;
            uint32_t af[16], bf[8];
#pragma unroll
            for (int mi = 0; mi < 4; ++mi)
                ldm_x4(af + mi * 4, slot + a_base[mi] + (uint32_t)(((kc + a_ch) ^ a_rx[mi]) << 4));
#pragma unroll
            for (int p = 0; p < 2; ++p)
                ldm_x4(bf + p * 4, slot + b_base[p] + (uint32_t)(((kc + b_ch) ^ b_rx[p]) << 4));
#pragma unroll
            for (int mi = 0; mi < 4; ++mi)
#pragma unroll
                for (int nj = 0; nj < 4; ++nj)
                    mma16816(acc[mi][nj], af + mi * 4, bf + nj * 2);
        }
    }
    __syncthreads();   // everyone done reading SMEM before Cs staging reuses it

    // -- epilogue: stage C1/C2 (fp32) + gamma to smem, then write y --
    float* Cs = (float*)dsm;                       // [2][128][CS_STRIDE]
    float* Gs = Cs + 2 * 128 * CS_STRIDE;          // [128]
    const int lr = lane >> 2;
    const int lc = (lane & 3) * 2;
    float* Cg = Cs + (size_t)grp * 128 * CS_STRIDE;
#pragma unroll
    for (int mi = 0; mi < 4; ++mi) {
#pragma unroll
        for (int nj = 0; nj < 4; ++nj) {
            float* p0 = Cg + (size_t)(wm + mi * 16 + lr) * CS_STRIDE + wn + nj * 8 + lc;
            *(float2*)p0                    = make_float2(acc[mi][nj][0], acc[mi][nj][1]);
            *(float2*)(p0 + 8 * CS_STRIDE)  = make_float2(acc[mi][nj][2], acc[mi][nj][3]);
        }
    }
    if (tid < 128) Gs[tid] = g_gamma[bm + tid];
    __syncthreads();

#pragma unroll
    for (int it = 0; it < 8; ++it) {
        int idx = tid + it * 256;          // 0..2047  (128 rows x 16 col-quads)
        int row = idx >> 4;
        int c4  = (idx & 15) * 4;
        int m = bm + row;
        int t = m & (TT - 1);
        float g  = Gs[row];
        float og = 1.f - g;

        float4 uu = *(const float4*)(u + (size_t)m * DD + bj + c4);
        float4 c1 = *(const float4*)(Cs + (size_t)row * CS_STRIDE + c4);
        float4 c2 = *(const float4*)(Cs + (size_t)(128 + row) * CS_STRIDE + c4);
        float4 xf = (t == 0)      ? uu : c1;
        float4 xb = (t == TT - 1) ? uu : c2;

        float4 out;
        out.x = g * (xf.x + xb.x) + og * uu.x;
        out.y = g * (xf.y + xb.y) + og * uu.y;
        out.z = g * (xf.z + xb.z) + og * uu.z;
        out.w = g * (xf.w + xb.w) + og * uu.w;
        *(float4*)(y + (size_t)m * DD + bj + c4) = out;
    }
}

// ---------------------------------------------------------------------------
// kernel_launch: inputs 0:u 1:WA(dead) 2:WB 3:WAf(dead) 4:WBf 5:w1 6:w2 7:b 8:Wc
// Output: [y | gamma | final] flattened f32.
// ---------------------------------------------------------------------------
extern "C" void kernel_launch(void* const* d_in, const int* in_sizes, int n_in,
                              void* d_out, int out_size) {
    (void)in_sizes; (void)n_in; (void)out_size;
    const float* u   = (const float*)d_in[0];
    const float* WB  = (const float*)d_in[2];
    const float* WBf = (const float*)d_in[4];
    const float* w1  = (const float*)d_in[5];
    const float* w2  = (const float*)d_in[6];
    const float* b   = (const float*)d_in[7];
    const float* Wc  = (const float*)d_in[8];

    float* y         = (float*)d_out;
    float* gamma_out = y + Y_ELEMS;
    float* final_out = gamma_out + G_ELEMS;

    cudaFuncSetAttribute(gemm_fused_kernel,
                         cudaFuncAttributeMaxDynamicSharedMemorySize, SMEM_DYN);

    convert_w_kernel<<<(2 * DD * KK) / 1024, 256>>>(WB, WBf);
    precompute_partial_kernel<<<dim3(DD / 256, 16), 256>>>(WB, WBf, w1, w2, Wc);
    precompute_reduce_kernel<<<DD / 256, 256>>>();
    gamma_final_kernel<<<ROWS / 8, 256>>>(u, w1, w2, b, Wc, gamma_out, final_out);
    gemm_fused_kernel<<<dim3(DD / XN, ROWS / BM), 256, SMEM_DYN>>>(u, y);
}

// round 17
// speedup vs baseline: 1.0618x; 1.0252x over previous
#include <cuda_runtime.h>
#include <cuda_fp16.h>
#include <math.h>
#include <stdint.h>

// ---------------------------------------------------------------------------
// Problem: u (8,4096,1024) f32. Outputs: y (8,4096,1024), gamma, final.
// Row-pair gamma kernel (SMEM vectors, 3 u-streams per 2 rows) emits u fp16;
// fused GEMM computes
//   C1[m] = u[m]   @ WB ^T (cols bj..bj+63)   (warps 0-3)
//   C2[m] = u[m+1] @ WBf^T (cols bj..bj+63)   (warps 4-7, +1 row shift)
// from ONE shared 129-row A tile, then writes y = g*(xf+xb)+(1-g)*u directly.
// GEMM identical to R13 (330us proven). 256 thr/CTA, 3-stage, 2 CTAs/SM.
// ---------------------------------------------------------------------------
#define BB 8
#define TT 4096
#define DD 1024
#define ROWS (BB * TT)              // 32768  (M)
#define KK   DD                     // 1024   (K)
#define Y_ELEMS   (ROWS * DD)
#define G_ELEMS   (ROWS)

// GEMM tiling
#define BM 128
#define XN 64                        // V-columns per CTA (each of C1, C2)
#define BK 64
#define STAGES 3
#define NCHUNK (KK / BK)             // 16
#define OFF_A 0                      // 129 rows x 128B
#define OFF_B 16640
#define STAGE_BYTES 33024            // A(16640) + B(16384)
#define SMEM_DYN (STAGES * STAGE_BYTES)   // 99072
#define CS_STRIDE 68                 // fp32 staging stride (bank-friendly)

// Device-global scratch (no cudaMalloc anywhere)
__device__ __half g_Af[(size_t)ROWS * KK];       // 64 MiB  (u in fp16)
__device__ __half g_Bf[(size_t)2 * DD * KK];     // 4 MiB: rows 0..1023 WB, 1024.. WBf
__device__ float  g_vecs[4 * DD];                // a1 | a2 | cB | cBf
__device__ float  g_part[16][4][DD];             // precompute partials
__device__ float  g_gamma[ROWS];

// ---------------------------------------------------------------------------
// PTX helpers (sm_80-class only: cp.async, ldmatrix, mma.sync)
// ---------------------------------------------------------------------------
__device__ __forceinline__ uint32_t smem_u32(const void* p) {
    uint32_t a;
    asm("{ .reg .u64 t; cvta.to.shared.u64 t, %1; cvt.u32.u64 %0, t; }"
        : "=r"(a) : "l"(p));
    return a;
}
__device__ __forceinline__ void cpasync16(uint32_t dst, const void* src) {
    asm volatile("cp.async.cg.shared.global [%0], [%1], 16;" :: "r"(dst), "l"(src));
}
#define CP_COMMIT() asm volatile("cp.async.commit_group;" ::: "memory")
#define CP_WAIT_1() asm volatile("cp.async.wait_group 1;" ::: "memory")
#define CP_WAIT_0() asm volatile("cp.async.wait_group 0;" ::: "memory")

__device__ __forceinline__ void ldm_x4(uint32_t* r, uint32_t addr) {
    asm volatile("ldmatrix.sync.aligned.m8n8.x4.shared.b16 {%0,%1,%2,%3}, [%4];"
                 : "=r"(r[0]), "=r"(r[1]), "=r"(r[2]), "=r"(r[3]) : "r"(addr));
}
__device__ __forceinline__ void mma16816(float* c, const uint32_t* a,
                                         const uint32_t* b) {
    asm volatile("mma.sync.aligned.m16n8k16.row.col.f32.f16.f16.f32 "
                 "{%0,%1,%2,%3}, {%4,%5,%6,%7}, {%8,%9}, {%0,%1,%2,%3};"
                 : "+f"(c[0]), "+f"(c[1]), "+f"(c[2]), "+f"(c[3])
                 : "r"(a[0]), "r"(a[1]), "r"(a[2]), "r"(a[3]),
                   "r"(b[0]), "r"(b[1]));
}
__device__ __forceinline__ float dot4(float4 a, float4 b) {
    return fmaf(a.x, b.x, fmaf(a.y, b.y, fmaf(a.z, b.z, a.w * b.w)));
}

// ---------------------------------------------------------------------------
// K0: [WB;WBf] -> fp16.
// ---------------------------------------------------------------------------
__global__ void convert_w_kernel(const float* __restrict__ WB,
                                 const float* __restrict__ WBf) {
    size_t i = ((size_t)blockIdx.x * 256 + threadIdx.x) * 4;
    const float* src = (i < (size_t)DD * DD) ? (WB + i) : (WBf + i - (size_t)DD * DD);
    float4 x = *(const float4*)src;
    union { __half h[4]; uint2 v; } H;
    H.h[0] = __float2half_rn(x.x);  H.h[1] = __float2half_rn(x.y);
    H.h[2] = __float2half_rn(x.z);  H.h[3] = __float2half_rn(x.w);
    *(uint2*)(g_Bf + i) = H.v;
}

// ---------------------------------------------------------------------------
// K1a/K1b: precompute a1 = w1@WB, a2 = w2@WBf, cB = Wc@WB, cBf = Wc@WBf.
// Two-phase, 64 CTAs, no atomics (deterministic): partials then reduce.
// ---------------------------------------------------------------------------
__global__ void precompute_partial_kernel(const float* __restrict__ WB,
                                          const float* __restrict__ WBf,
                                          const float* __restrict__ w1,
                                          const float* __restrict__ w2,
                                          const float* __restrict__ Wc) {
    int d  = blockIdx.x * 256 + threadIdx.x;   // 0..1023
    int e0 = blockIdx.y * 64;
    float a1 = 0.f, a2 = 0.f, cB = 0.f, cBf = 0.f;
#pragma unroll 8
    for (int e = e0; e < e0 + 64; ++e) {
        float wb = WB[e * DD + d];
        float wf = WBf[e * DD + d];
        a1  += w1[e] * wb;
        cB  += Wc[e] * wb;
        a2  += w2[e] * wf;
        cBf += Wc[e] * wf;
    }
    g_part[blockIdx.y][0][d] = a1;
    g_part[blockIdx.y][1][d] = a2;
    g_part[blockIdx.y][2][d] = cB;
    g_part[blockIdx.y][3][d] = cBf;
}

__global__ void precompute_reduce_kernel() {
    int d = blockIdx.x * 256 + threadIdx.x;    // 0..1023
#pragma unroll
    for (int v = 0; v < 4; ++v) {
        float s = 0.f;
#pragma unroll
        for (int k = 0; k < 16; ++k) s += g_part[k][v][d];
        g_vecs[v * DD + d] = s;
    }
}

// ---------------------------------------------------------------------------
// K2: row-pair gamma + final + fp16 u emit. One warp per TWO rows:
//   U0 = u[2r], U1 = u[2r+1], U2 = u[2r+2] (or u[2r+1] if rowB is t==T-1).
// 5 SMEM vectors shared by both rows; 3 LDG streams serve 2 rows.
// rowA (even) may be t==0; rowB (odd) may be t==T-1. Interior math order
// identical to R16 (dot4 + 5-step shfl reduce) -> bit-identical rel_err.
// grid ROWS/16 blocks x 256 thr.
// ---------------------------------------------------------------------------
__global__ __launch_bounds__(256, 4)
void gamma_final_kernel(const float* __restrict__ u,
                        const float* __restrict__ w1,
                        const float* __restrict__ w2,
                        const float* __restrict__ bias,
                        const float* __restrict__ Wc,
                        float* __restrict__ gamma_out,
                        float* __restrict__ final_out) {
    __shared__ __align__(16) float sv[7 * DD];   // a1|a2|cB|cBf|Wc|w1|w2

    {   // cooperative stage: one float4 per thread per vector
        int i = threadIdx.x * 4;
        *(float4*)(sv + 0 * DD + i) = *(const float4*)(g_vecs + i);
        *(float4*)(sv + 1 * DD + i) = *(const float4*)(g_vecs + DD + i);
        *(float4*)(sv + 2 * DD + i) = *(const float4*)(g_vecs + 2 * DD + i);
        *(float4*)(sv + 3 * DD + i) = *(const float4*)(g_vecs + 3 * DD + i);
        *(float4*)(sv + 4 * DD + i) = *(const float4*)(Wc + i);
        *(float4*)(sv + 5 * DD + i) = *(const float4*)(w1 + i);
        *(float4*)(sv + 6 * DD + i) = *(const float4*)(w2 + i);
    }
    __syncthreads();

    const int rowA = blockIdx.x * 16 + (threadIdx.x >> 5) * 2;
    const int rowB = rowA + 1;
    const int lane = threadIdx.x & 31;
    const int tA = rowA & (TT - 1);
    const bool is_t0 = (tA == 0);             // only rowA (even) can be t==0
    const bool is_tL = (tA == TT - 2);        // rowB == T-1  <=>  tA == T-2

    const float* pU0 = u + (size_t)rowA * DD;
    const float* pU1 = pU0 + DD;              // u[rowB]
    const float* pU2 = is_tL ? pU1 : pU1 + DD;  // u2 for rowB (clamped at T-1)

    float s1a = 0.f, cfa = 0.f, cua = 0.f, s2a = 0.f, cba = 0.f;
    float s1b = 0.f, cfb = 0.f, cub = 0.f, s2b = 0.f, cbb = 0.f;
    float sba = 0.f, sbb = 0.f;
#pragma unroll
    for (int it = 0; it < 8; ++it) {
        int i = lane * 4 + it * 128;
        float4 U0 = *(const float4*)(pU0 + i);
        float4 U1 = *(const float4*)(pU1 + i);
        float4 U2 = *(const float4*)(pU2 + i);
        float4 x1 = *(const float4*)(sv + 0 * DD + i);
        float4 x2 = *(const float4*)(sv + 1 * DD + i);
        float4 xc = *(const float4*)(sv + 2 * DD + i);
        float4 xb = *(const float4*)(sv + 3 * DD + i);
        float4 wc = *(const float4*)(sv + 4 * DD + i);

        union { __half h[4]; uint2 v; } H0, H1;
        H0.h[0] = __float2half_rn(U0.x);  H0.h[1] = __float2half_rn(U0.y);
        H0.h[2] = __float2half_rn(U0.z);  H0.h[3] = __float2half_rn(U0.w);
        H1.h[0] = __float2half_rn(U1.x);  H1.h[1] = __float2half_rn(U1.y);
        H1.h[2] = __float2half_rn(U1.z);  H1.h[3] = __float2half_rn(U1.w);
        *(uint2*)(g_Af + (size_t)rowA * DD + i) = H0.v;
        *(uint2*)(g_Af + (size_t)rowB * DD + i) = H1.v;

        s1a += dot4(U0, x1);  cfa += dot4(U0, xc);  cua += dot4(U0, wc);
        s2a += dot4(U1, x2);  cba += dot4(U1, xb);
        s1b += dot4(U1, x1);  cfb += dot4(U1, xc);  cub += dot4(U1, wc);
        s2b += dot4(U2, x2);  cbb += dot4(U2, xb);
        if (is_t0) sba += dot4(U0, *(const float4*)(sv + 5 * DD + i));  // u.w1
        if (is_tL) sbb += dot4(U2, *(const float4*)(sv + 6 * DD + i));  // u.w2
    }
#pragma unroll
    for (int off = 16; off > 0; off >>= 1) {
        s1a += __shfl_down_sync(0xffffffffu, s1a, off);
        cfa += __shfl_down_sync(0xffffffffu, cfa, off);
        cua += __shfl_down_sync(0xffffffffu, cua, off);
        s2a += __shfl_down_sync(0xffffffffu, s2a, off);
        cba += __shfl_down_sync(0xffffffffu, cba, off);
        s1b += __shfl_down_sync(0xffffffffu, s1b, off);
        cfb += __shfl_down_sync(0xffffffffu, cfb, off);
        cub += __shfl_down_sync(0xffffffffu, cub, off);
        s2b += __shfl_down_sync(0xffffffffu, s2b, off);
        cbb += __shfl_down_sync(0xffffffffu, cbb, off);
        sba += __shfl_down_sync(0xffffffffu, sba, off);
        sbb += __shfl_down_sync(0xffffffffu, sbb, off);
    }
    if (lane == 0) {
        float bv = bias[0];
        if (is_t0) { s1a = sba; cfa = cua; }
        float ga   = 1.f / (1.f + expf(-(s1a + s2a + bv)));
        float fina = 1.f / (1.f + expf(-(ga * (cfa + cba) + (1.f - ga) * cua)));
        g_gamma[rowA]   = ga;
        gamma_out[rowA] = ga;
        final_out[rowA] = fina;

        if (is_tL) { s2b = sbb; cbb = cub; }
        float gb   = 1.f / (1.f + expf(-(s1b + s2b + bv)));
        float finb = 1.f / (1.f + expf(-(gb * (cfb + cbb) + (1.f - gb) * cub)));
        g_gamma[rowB]   = gb;
        gamma_out[rowB] = gb;
        final_out[rowB] = finb;
    }
}

// ---------------------------------------------------------------------------
// K3: fused HMMA GEMM + y epilogue. 256 threads, 2 CTAs/SM, ONE barrier/chunk.
// (exact R13 version, 330us proven)  grid (16, 256).
// ---------------------------------------------------------------------------
__global__ __launch_bounds__(256, 2)
void gemm_fused_kernel(const float* __restrict__ u, float* __restrict__ y) {
    extern __shared__ __align__(128) char dsm[];
    const uint32_t sbase = smem_u32(dsm);

    const int tid  = threadIdx.x;
    const int wid  = tid >> 5;
    const int lane = tid & 31;
    const int bm = blockIdx.y * BM;
    const int bj = blockIdx.x * XN;     // V column offset (0..960)

    const int grp = wid >> 2;           // 0: C1 (row m), 1: C2 (row m+1)
    const int w2  = wid & 3;
    const int wm  = (w2 >> 1) * 64;     // warp m offset (0/64)
    const int wn  = (w2 & 1) * 32;      // warp n offset within 64 (0/32)

    const int lrow = tid >> 3;          // 0..31 (+j*32)
    const int lchk = tid & 7;
    auto load_stage = [&](int kchunk, int slot) {
        uint32_t sb = sbase + slot * STAGE_BYTES;
        int kb = kchunk * BK;
#pragma unroll
        for (int j = 0; j < 4; ++j) {
            int r = lrow + j * 32;
            uint32_t so = (uint32_t)(r * 128) + (uint32_t)((lchk ^ (r & 7)) << 4);
            int rb = bj + r + ((r >> 6) * (DD - XN));   // rows 0-63: WB, 64-127: WBf
            cpasync16(sb + OFF_A + so, g_Af + (size_t)(bm + r) * KK + kb + lchk * 8);
            cpasync16(sb + OFF_B + so, g_Bf + (size_t)rb * KK + kb + lchk * 8);
        }
        if (tid < 8) {                  // A row 128 (clamped at last CTA)
            int ra = bm + 128;  if (ra > ROWS - 1) ra = ROWS - 1;
            cpasync16(sb + OFF_A + 128 * 128 + tid * 16,
                      g_Af + (size_t)ra * KK + kb + tid * 8);
        }
    };

    uint32_t a_base[4], b_base[2];
    int a_rx[4], b_rx[2];
    const int a_ch = lane >> 4;
    const int b_ch = (lane >> 3) & 1;
#pragma unroll
    for (int mi = 0; mi < 4; ++mi) {
        int r = wm + mi * 16 + (lane & 15) + grp;
        a_base[mi] = OFF_A + (uint32_t)(r * 128);
        a_rx[mi] = r & 7;
    }
#pragma unroll
    for (int p = 0; p < 2; ++p) {
        int r = grp * 64 + wn + p * 16 + (lane & 7) + ((lane >> 4) << 3);
        b_base[p] = OFF_B + (uint32_t)(r * 128);
        b_rx[p] = r & 7;
    }

    float acc[4][4][4];
#pragma unroll
    for (int mi = 0; mi < 4; ++mi)
#pragma unroll
        for (int nj = 0; nj < 4; ++nj)
#pragma unroll
            for (int q = 0; q < 4; ++q) acc[mi][nj][q] = 0.f;

    load_stage(0, 0); CP_COMMIT();
    load_stage(1, 1); CP_COMMIT();

    for (int c = 0; c < NCHUNK; ++c) {
        if (c < NCHUNK - 1) CP_WAIT_1(); else CP_WAIT_0();
        __syncthreads();

        if (c + 2 < NCHUNK) {
            load_stage(c + 2, (c + 2) % STAGES);
            CP_COMMIT();
        }

        const uint32_t slot = sbase + (uint32_t)((c % STAGES) * STAGE_BYTES);

#pragma unroll
        for (int ks = 0; ks < 4; ++ks) {
            const int kc = ks * 2;
            uint32_t af[16], bf[8];
#pragma unroll
            for (int mi = 0; mi < 4; ++mi)
                ldm_x4(af + mi * 4, slot + a_base[mi] + (uint32_t)(((kc + a_ch) ^ a_rx[mi]) << 4));
#pragma unroll
            for (int p = 0; p < 2; ++p)
                ldm_x4(bf + p * 4, slot + b_base[p] + (uint32_t)(((kc + b_ch) ^ b_rx[p]) << 4));
#pragma unroll
            for (int mi = 0; mi < 4; ++mi)
#pragma unroll
                for (int nj = 0; nj < 4; ++nj)
                    mma16816(acc[mi][nj], af + mi * 4, bf + nj * 2);
        }
    }
    __syncthreads();   // everyone done reading SMEM before Cs staging reuses it

    // -- epilogue: stage C1/C2 (fp32) + gamma to smem, then write y --
    float* Cs = (float*)dsm;                       // [2][128][CS_STRIDE]
    float* Gs = Cs + 2 * 128 * CS_STRIDE;          // [128]
    const int lr = lane >> 2;
    const int lc = (lane & 3) * 2;
    float* Cg = Cs + (size_t)grp * 128 * CS_STRIDE;
#pragma unroll
    for (int mi = 0; mi < 4; ++mi) {
#pragma unroll
        for (int nj = 0; nj < 4; ++nj) {
            float* p0 = Cg + (size_t)(wm + mi * 16 + lr) * CS_STRIDE + wn + nj * 8 + lc;
            *(float2*)p0                    = make_float2(acc[mi][nj][0], acc[mi][nj][1]);
            *(float2*)(p0 + 8 * CS_STRIDE)  = make_float2(acc[mi][nj][2], acc[mi][nj][3]);
        }
    }
    if (tid < 128) Gs[tid] = g_gamma[bm + tid];
    __syncthreads();

#pragma unroll
    for (int it = 0; it < 8; ++it) {
        int idx = tid + it * 256;          // 0..2047  (128 rows x 16 col-quads)
        int row = idx >> 4;
        int c4  = (idx & 15) * 4;
        int m = bm + row;
        int t = m & (TT - 1);
        float g  = Gs[row];
        float og = 1.f - g;

        float4 uu = *(const float4*)(u + (size_t)m * DD + bj + c4);
        float4 c1 = *(const float4*)(Cs + (size_t)row * CS_STRIDE + c4);
        float4 c2 = *(const float4*)(Cs + (size_t)(128 + row) * CS_STRIDE + c4);
        float4 xf = (t == 0)      ? uu : c1;
        float4 xb = (t == TT - 1) ? uu : c2;

        float4 out;
        out.x = g * (xf.x + xb.x) + og * uu.x;
        out.y = g * (xf.y + xb.y) + og * uu.y;
        out.z = g * (xf.z + xb.z) + og * uu.z;
        out.w = g * (xf.w + xb.w) + og * uu.w;
        *(float4*)(y + (size_t)m * DD + bj + c4) = out;
    }
}

// ---------------------------------------------------------------------------
// kernel_launch: inputs 0:u 1:WA(dead) 2:WB 3:WAf(dead) 4:WBf 5:w1 6:w2 7:b 8:Wc
// Output: [y | gamma | final] flattened f32.
// ---------------------------------------------------------------------------
extern "C" void kernel_launch(void* const* d_in, const int* in_sizes, int n_in,
                              void* d_out, int out_size) {
    (void)in_sizes; (void)n_in; (void)out_size;
    const float* u   = (const float*)d_in[0];
    const float* WB  = (const float*)d_in[2];
    const float* WBf = (const float*)d_in[4];
    const float* w1  = (const float*)d_in[5];
    const float* w2  = (const float*)d_in[6];
    const float* b   = (const float*)d_in[7];
    const float* Wc  = (const float*)d_in[8];

    float* y         = (float*)d_out;
    float* gamma_out = y + Y_ELEMS;
    float* final_out = gamma_out + G_ELEMS;

    cudaFuncSetAttribute(gemm_fused_kernel,
                         cudaFuncAttributeMaxDynamicSharedMemorySize, SMEM_DYN);

    convert_w_kernel<<<(2 * DD * KK) / 1024, 256>>>(WB, WBf);
    precompute_partial_kernel<<<dim3(DD / 256, 16), 256>>>(WB, WBf, w1, w2, Wc);
    precompute_reduce_kernel<<<DD / 256, 256>>>();
    gamma_final_kernel<<<ROWS / 16, 256>>>(u, w1, w2, b, Wc, gamma_out, final_out);
    gemm_fused_kernel<<<dim3(DD / XN, ROWS / BM), 256, SMEM_DYN>>>(u, y);
}